// round 3
// baseline (speedup 1.0000x reference)
#include <cuda_runtime.h>
#include <cstdint>

// ---------------------------------------------------------------------------
// Problem constants
// ---------------------------------------------------------------------------
#define NLEV 5
#define BATCH 4
#define PRE_NMS 2000
#define POST_NMS 1000
#define NBL (BATCH * NLEV)          // 20 (batch, level) pairs
#define SORT_CAP 4096               // bitonic capacity for per-level top-k
#define TOTCAT 4768                 // 4*1000 + 768 concatenated entries
#define SPILL_PER_B 261888          // sum of A[l]

__constant__ int c_A[NLEV]      = {196608, 49152, 12288, 3072, 768};
__constant__ int c_K[NLEV]      = {2000, 2000, 2000, 2000, 768};
__constant__ int c_KP[NLEV]     = {1000, 1000, 1000, 1000, 768};
__constant__ int c_stride[NLEV] = {4, 8, 16, 32, 64};
__constant__ int c_grid[NLEV]   = {256, 128, 64, 32, 16};
__constant__ int c_base[NLEV]   = {32, 64, 128, 256, 512};
__constant__ int c_spillOff[NLEV] = {0, 196608, 245760, 258048, 261120};

// ---------------------------------------------------------------------------
// Device scratch (static allocation only — no cudaMalloc allowed)
// ---------------------------------------------------------------------------
__device__ int                 d_topIdx [NBL * PRE_NMS];
__device__ float               d_topScore[NBL * PRE_NMS];
__device__ float4              d_topBoxes[NBL * PRE_NMS];
__device__ unsigned long long  d_mask   [NBL * PRE_NMS * 32];
__device__ float               d_lvlScore[NBL * POST_NMS];
__device__ int                 d_lvlPos  [NBL * POST_NMS];
__device__ unsigned long long  d_spill  [BATCH * SPILL_PER_B];   // ~8.4 MB

// ---------------------------------------------------------------------------
// Helpers
// ---------------------------------------------------------------------------
__device__ __forceinline__ unsigned ordf(float f) {
    unsigned u = __float_as_uint(f);
    return (u & 0x80000000u) ? ~u : (u | 0x80000000u);
}
__device__ __forceinline__ float iordf(unsigned u) {
    unsigned v = (u & 0x80000000u) ? (u & 0x7FFFFFFFu) : ~u;
    return __uint_as_float(v);
}

// Warp-aggregated append: full warp must execute (use padded loops).
__device__ __forceinline__ int warpAppend(int* ctr, bool pred) {
    unsigned m = __ballot_sync(0xffffffffu, pred);
    int lane = threadIdx.x & 31;
    int base = 0;
    if (m != 0) {
        int leader = __ffs(m) - 1;
        if (lane == leader) base = atomicAdd(ctr, __popc(m));
        base = __shfl_sync(0xffffffffu, base, leader);
    }
    return pred ? base + __popc(m & ((1u << lane) - 1u)) : -1;
}

// ---------------------------------------------------------------------------
// Kernel 1: per-(b,l) EXACT top-K selection (stable: score desc, idx asc).
// Radix select 11+11+10 bits with warp-aggregated atomics; pass2 fused with
// compaction of bucket>b1 keys and spill of bucket==b1 keys to global scratch
// so that pass3 + final compaction touch only the spill list.
// ---------------------------------------------------------------------------
__global__ __launch_bounds__(1024)
void topk_kernel(const float* __restrict__ p0, const float* __restrict__ p1,
                 const float* __restrict__ p2, const float* __restrict__ p3,
                 const float* __restrict__ p4) {
    const int bl = blockIdx.x;
    const int b = bl / NLEV, l = bl % NLEV;
    const float* pr;
    switch (l) {
        case 0: pr = p0; break; case 1: pr = p1; break; case 2: pr = p2; break;
        case 3: pr = p3; break; default: pr = p4; break;
    }
    const int A = c_A[l];
    const int K = c_K[l];
    const float2* base2 = (const float2*)(pr + (size_t)b * A * 2);
    unsigned long long* spill = d_spill + (size_t)b * SPILL_PER_B + c_spillOff[l];
    const int tid = threadIdx.x;
    const int lane = tid & 31;

    __shared__ int hist[2048];
    __shared__ unsigned long long cand[SORT_CAP];
    __shared__ int s_b1, s_k1, s_b2, s_k2, s_b3, s_cnt, s_cntHi, s_cntSp;

    // ---- Pass 1: histogram of bits [31:21] (warp-aggregated atomics) ----
    for (int i = tid; i < 2048; i += 1024) hist[i] = 0;
    __syncthreads();
    for (int i = tid; i < A; i += 1024) {
        unsigned bkt = ordf(base2[i].x) >> 21;
        unsigned mm = __match_any_sync(0xffffffffu, bkt);
        if (lane == (__ffs(mm) - 1)) atomicAdd(&hist[bkt], __popc(mm));
    }
    __syncthreads();
    if (tid == 0) {
        int cum = 0, bsel = 0, krem = K;
        for (int bkt = 2047; bkt >= 0; --bkt) {
            int c = hist[bkt];
            if (cum + c >= K) { bsel = bkt; krem = K - cum; break; }
            cum += c;
        }
        s_b1 = bsel; s_k1 = krem; s_cntHi = 0; s_cntSp = 0;
    }
    __syncthreads();
    const unsigned b1 = (unsigned)s_b1;

    // ---- Pass 2 (fused): compact bucket>b1 into cand, spill bucket==b1,
    //      build hist2 over bits [20:10] of spilled keys ----
    for (int i = tid; i < 2048; i += 1024) hist[i] = 0;
    __syncthreads();
    {
        const int rounds = (A + 1023) >> 10;
        for (int r = 0; r < rounds; ++r) {
            int i = tid + (r << 10);
            bool in = i < A;
            unsigned u = 0;
            if (in) u = ordf(base2[i].x);
            unsigned bkt = u >> 21;
            unsigned long long key = ((unsigned long long)u << 32) | (unsigned)(~i);

            int pHi = warpAppend(&s_cntHi, in && (bkt > b1));
            if (pHi >= 0 && pHi < SORT_CAP) cand[pHi] = key;

            bool sp = in && (bkt == b1);
            int pSp = warpAppend(&s_cntSp, sp);
            if (sp) {
                spill[pSp] = key;
                atomicAdd(&hist[(u >> 10) & 0x7FFu], 1);
            }
        }
    }
    __syncthreads();
    const int cntHi = min(s_cntHi, SORT_CAP);
    const int M2 = s_cntSp;
    const int K1 = K - cntHi;
    if (tid == 0) {
        int cum = 0, bsel = 0, krem = K1;
        for (int bkt = 2047; bkt >= 0; --bkt) {
            int c = hist[bkt];
            if (cum + c >= K1) { bsel = bkt; krem = K1 - cum; break; }
            cum += c;
        }
        s_b2 = bsel; s_k2 = krem;
    }
    __syncthreads();
    const unsigned b2 = (unsigned)s_b2;
    const int K2 = s_k2;

    // ---- Pass 3: histogram of bits [9:0] over spill entries matching b2 ----
    for (int i = tid; i < 1024; i += 1024) hist[i] = 0;
    __syncthreads();
    for (int i = tid; i < M2; i += 1024) {
        unsigned u = (unsigned)(spill[i] >> 32);
        if (((u >> 10) & 0x7FFu) == b2) atomicAdd(&hist[u & 0x3FFu], 1);
    }
    __syncthreads();
    if (tid == 0) {
        int cum = 0, bsel = 0;
        for (int bkt = 1023; bkt >= 0; --bkt) {
            int c = hist[bkt];
            if (cum + c >= K2) { bsel = bkt; break; }
            cum += c;
        }
        s_b3 = bsel; s_cnt = cntHi;
    }
    __syncthreads();
    const unsigned T = (b1 << 21) | (b2 << 10) | (unsigned)s_b3;

    // ---- Compact spill entries with u >= T into cand after cntHi ----
    {
        const int rounds = (M2 + 1023) >> 10;
        for (int r = 0; r < rounds; ++r) {
            int i = tid + (r << 10);
            bool in = i < M2;
            unsigned long long key = 0;
            if (in) key = spill[i];
            bool take = in && ((unsigned)(key >> 32) >= T);
            int p = warpAppend(&s_cnt, take);
            if (take && p < SORT_CAP) cand[p] = key;
        }
    }
    __syncthreads();
    const int M = min(s_cnt, SORT_CAP);
    for (int i = tid; i < SORT_CAP; i += 1024)
        if (i >= M) cand[i] = 0ull;
    __syncthreads();

    // ---- Bitonic sort descending (4096 keys) ----
    for (int k = 2; k <= SORT_CAP; k <<= 1) {
        for (int j = k >> 1; j > 0; j >>= 1) {
            for (int idx = tid; idx < SORT_CAP; idx += 1024) {
                int ixj = idx ^ j;
                if (ixj > idx) {
                    unsigned long long a = cand[idx], c2 = cand[ixj];
                    bool desc = (idx & k) == 0;
                    if (desc ? (a < c2) : (a > c2)) { cand[idx] = c2; cand[ixj] = a; }
                }
            }
            __syncthreads();
        }
    }

    for (int j = tid; j < K; j += 1024) {
        unsigned long long key = cand[j];
        d_topIdx [bl * PRE_NMS + j] = (int)(~(unsigned)key);
        d_topScore[bl * PRE_NMS + j] = iordf((unsigned)(key >> 32));
    }
}

// ---------------------------------------------------------------------------
// Kernel 2: decode + clip. All FP via _rn intrinsics (no FMA contraction),
// exp via expf (libdevice) — bit-matches the XLA reference.
// ---------------------------------------------------------------------------
__global__ __launch_bounds__(256)
void decode_kernel(const float* __restrict__ r0, const float* __restrict__ r1,
                   const float* __restrict__ r2, const float* __restrict__ r3,
                   const float* __restrict__ r4, const float* __restrict__ info) {
    const int bl = blockIdx.y;
    const int b = bl / NLEV, l = bl % NLEV;
    const int j = blockIdx.x * 256 + threadIdx.x;
    if (j >= c_K[l]) return;

    const float* rg;
    switch (l) {
        case 0: rg = r0; break; case 1: rg = r1; break; case 2: rg = r2; break;
        case 3: rg = r3; break; default: rg = r4; break;
    }
    const int A = c_A[l];
    const int g = c_grid[l];
    const float strf = (float)c_stride[l];

    const int idx = d_topIdx[bl * PRE_NMS + j];
    const int cell = idx / 3, a = idx - cell * 3;
    const int iy = cell / g, ix = cell - iy * g;

    float cx = __fmul_rn((float)ix + 0.5f, strf);
    float cy = __fmul_rn((float)iy + 0.5f, strf);

    double r = (a == 0) ? 0.5 : ((a == 1) ? 1.0 : 2.0);
    double sb = (double)c_base[l] * 8.0;
    float aw = (float)(sb * sqrt(1.0 / r));
    float ah = (float)(sb * sqrt(r));

    float x1a = __fsub_rn(cx, __fmul_rn(0.5f, aw));
    float y1a = __fsub_rn(cy, __fmul_rn(0.5f, ah));
    float x2a = __fadd_rn(cx, __fmul_rn(0.5f, aw));
    float y2a = __fadd_rn(cy, __fmul_rn(0.5f, ah));

    float wa = __fsub_rn(x2a, x1a);
    float ha = __fsub_rn(y2a, y1a);
    float cxa = __fadd_rn(x1a, __fmul_rn(0.5f, wa));
    float cya = __fadd_rn(y1a, __fmul_rn(0.5f, ha));

    const float* rp = rg + ((size_t)b * A + idx) * 4;
    float dx = rp[0], dy = rp[1], dw = rp[2], dh = rp[3];

    float ncx = __fadd_rn(__fmul_rn(dx, wa), cxa);
    float ncy = __fadd_rn(__fmul_rn(dy, ha), cya);
    float nw  = __fmul_rn(expf(dw), wa);
    float nh  = __fmul_rn(expf(dh), ha);

    float x1 = __fsub_rn(ncx, __fmul_rn(0.5f, nw));
    float y1 = __fsub_rn(ncy, __fmul_rn(0.5f, nh));
    float x2 = __fadd_rn(ncx, __fmul_rn(0.5f, nw));
    float y2 = __fadd_rn(ncy, __fmul_rn(0.5f, nh));

    const float* in2 = info + b * 3;
    float H = __fsub_rn(in2[0], 1.0f);
    float W = __fsub_rn(in2[1], 1.0f);
    x1 = fminf(fmaxf(x1, 0.0f), W);
    x2 = fminf(fmaxf(x2, 0.0f), W);
    y1 = fminf(fmaxf(y1, 0.0f), H);
    y2 = fminf(fmaxf(y2, 0.0f), H);

    d_topBoxes[bl * PRE_NMS + j] = make_float4(x1, y1, x2, y2);
}

// ---------------------------------------------------------------------------
// Kernel 3: NMS suppression-mask — upper-triangular tiles only (bx >= by).
// ---------------------------------------------------------------------------
__global__ __launch_bounds__(64)
void nms_mask_kernel() {
    if (blockIdx.x < blockIdx.y) return;          // strictly-lower tiles: all zero
    const int bl = blockIdx.z;
    const int l = bl % NLEV;
    const int N = c_K[l];
    const int rowStart = blockIdx.y * 64;
    const int colStart = blockIdx.x * 64;
    if (rowStart >= N || colStart >= N) return;

    __shared__ float4 cbx[64];
    const int t = threadIdx.x;
    int jj = colStart + t;
    cbx[t] = (jj < N) ? d_topBoxes[bl * PRE_NMS + jj] : make_float4(0.f, 0.f, 0.f, 0.f);
    __syncthreads();

    const int i = rowStart + t;
    if (i >= N) return;
    float4 bi = d_topBoxes[bl * PRE_NMS + i];
    float ai = __fmul_rn(fmaxf(__fsub_rn(bi.z, bi.x), 0.0f),
                         fmaxf(__fsub_rn(bi.w, bi.y), 0.0f));
    unsigned long long bits = 0ull;
    #pragma unroll 8
    for (int jl = 0; jl < 64; ++jl) {
        int jg = colStart + jl;
        if (jg <= i || jg >= N) continue;
        float4 bj = cbx[jl];
        float xx1 = fmaxf(bi.x, bj.x), yy1 = fmaxf(bi.y, bj.y);
        float xx2 = fminf(bi.z, bj.z), yy2 = fminf(bi.w, bj.w);
        float w = fmaxf(__fsub_rn(xx2, xx1), 0.0f);
        float h = fmaxf(__fsub_rn(yy2, yy1), 0.0f);
        float inter = __fmul_rn(w, h);
        float aj = __fmul_rn(fmaxf(__fsub_rn(bj.z, bj.x), 0.0f),
                             fmaxf(__fsub_rn(bj.w, bj.y), 0.0f));
        float uni = fmaxf(__fsub_rn(__fadd_rn(ai, aj), inter), 1e-9f);
        float iou = __fdiv_rn(inter, uni);
        if (iou > 0.7f) bits |= (1ull << jl);
    }
    d_mask[((size_t)bl * PRE_NMS + i) * 32 + blockIdx.x] = bits;
}

// ---------------------------------------------------------------------------
// Kernel 4: chunked NMS reduce.
// Diagonal mask words pre-staged in smem; per 64-row chunk all 32 lanes
// redundantly resolve keep bits from smem (register-chain only, no shfl in
// the serial path), then column-lanes apply kept-row masks with batched,
// latency-hidden global loads. One shfl per chunk. Then stable compaction.
// ---------------------------------------------------------------------------
__global__ __launch_bounds__(1024)
void nms_reduce_kernel() {
    const int bl = blockIdx.x;
    const int l = bl % NLEV;
    const int N = c_K[l];
    const int KP = c_KP[l];
    const int tid = threadIdx.x;

    __shared__ unsigned long long s_diag[PRE_NMS];   // 16 KB
    __shared__ unsigned long long s_keep[32];
    __shared__ int sA[2048], sB[2048];

    const unsigned long long* mbase = d_mask + (size_t)bl * PRE_NMS * 32;

    // Stage diagonal-tile words: s_diag[i] = mask[i][i>>6]
    for (int i = tid; i < N; i += 1024)
        s_diag[i] = mbase[(size_t)i * 32 + (i >> 6)];
    __syncthreads();

    const int NC = (N + 63) >> 6;
    if (tid < 32) {
        const int lane = tid;
        unsigned long long rem = 0ull;
        const unsigned long long* mp = mbase + lane;
        for (int c = 0; c < NC; ++c) {
            const int cbase = c << 6;
            const int nr = min(64, N - cbase);
            unsigned long long r = __shfl_sync(0xffffffffu, rem, c);
            unsigned long long keep = 0ull;
            #pragma unroll 4
            for (int k = 0; k < nr; ++k) {
                if (!((r >> k) & 1ull)) { r |= s_diag[cbase + k]; keep |= (1ull << k); }
            }
            if (lane == 0) s_keep[c] = keep;
            if (lane > c && lane < NC) {
                unsigned long long a0 = 0, a1 = 0, a2 = 0, a3 = 0;
                for (int k = 0; k < nr; k += 4) {          // nr is 64 or 16
                    unsigned long long m0 = mp[(size_t)(cbase + k) * 32];
                    unsigned long long m1 = mp[(size_t)(cbase + k + 1) * 32];
                    unsigned long long m2 = mp[(size_t)(cbase + k + 2) * 32];
                    unsigned long long m3 = mp[(size_t)(cbase + k + 3) * 32];
                    if ((keep >> k) & 1ull)       a0 |= m0;
                    if ((keep >> (k + 1)) & 1ull) a1 |= m1;
                    if ((keep >> (k + 2)) & 1ull) a2 |= m2;
                    if ((keep >> (k + 3)) & 1ull) a3 |= m3;
                }
                rem |= (a0 | a1) | (a2 | a3);
            }
        }
    }
    __syncthreads();

    // keep flags -> stable compaction: kept in score order, then suppressed
    for (int j = tid; j < 2048; j += 1024) {
        int kept = 0;
        if (j < N) kept = (int)((s_keep[j >> 6] >> (j & 63)) & 1ull);
        sA[j] = kept;
    }
    __syncthreads();

    int* src = sA; int* dst = sB;
    for (int off = 1; off < 2048; off <<= 1) {
        for (int j = tid; j < 2048; j += 1024)
            dst[j] = src[j] + ((j >= off) ? src[j - off] : 0);
        __syncthreads();
        int* t = src; src = dst; dst = t;
    }
    const int total = src[2047];

    for (int j = tid; j < N; j += 1024) {
        int kept = (int)((s_keep[j >> 6] >> (j & 63)) & 1ull);
        int incl = src[j];
        if (kept) {
            int rank = incl - 1;
            if (rank < KP) {
                d_lvlScore[bl * POST_NMS + rank] = d_topScore[bl * PRE_NMS + j];
                d_lvlPos  [bl * POST_NMS + rank] = j;
            }
        } else {
            int rank = total + (j - incl);
            if (rank < KP) {
                d_lvlScore[bl * POST_NMS + rank] = -1.0f;
                d_lvlPos  [bl * POST_NMS + rank] = j;
            }
        }
    }
}

// ---------------------------------------------------------------------------
// Kernel 5: final cross-level top-1000 via rank-by-binary-search.
// ---------------------------------------------------------------------------
__global__ __launch_bounds__(1024)
void final_kernel(float* __restrict__ out) {
    const int b = blockIdx.x;
    const int tid = threadIdx.x;
    __shared__ unsigned long long key[TOTCAT];

    for (int c = tid; c < TOTCAT; c += 1024) {
        int l = (c < 4000) ? (c / 1000) : 4;
        int pos = c - l * 1000;
        float s = d_lvlScore[(b * NLEV + l) * POST_NMS + pos];
        key[c] = ((unsigned long long)ordf(s) << 32) | (unsigned)(~c);
    }
    __syncthreads();

    const int segN[NLEV] = {1000, 1000, 1000, 1000, 768};
    for (int c = tid; c < TOTCAT; c += 1024) {
        unsigned long long ke = key[c];
        int rank = 0;
        #pragma unroll
        for (int l2 = 0; l2 < NLEV; ++l2) {
            const int base2 = l2 * 1000;
            int lo = 0, hi = segN[l2];
            while (lo < hi) {
                int mid = (lo + hi) >> 1;
                if (key[base2 + mid] > ke) lo = mid + 1; else hi = mid;
            }
            rank += lo;
        }
        if (rank < POST_NMS) {
            unsigned hi32 = (unsigned)(ke >> 32);
            int l = (c < 4000) ? (c / 1000) : 4;
            int pos = c - l * 1000;
            float* o = out + ((size_t)b * POST_NMS + rank) * 5;
            o[0] = (float)b;
            if (hi32 & 0x80000000u) {   // score >= 0
                int blx = b * NLEV + l;
                int j = d_lvlPos[blx * POST_NMS + pos];
                float4 bx = d_topBoxes[blx * PRE_NMS + j];
                o[1] = bx.x; o[2] = bx.y; o[3] = bx.z; o[4] = bx.w;
            } else {
                o[1] = 0.0f; o[2] = 0.0f; o[3] = 0.0f; o[4] = 0.0f;
            }
        }
    }
}

// ---------------------------------------------------------------------------
// Launcher — inputs identified BY ELEMENT COUNT (all 11 sizes distinct).
// ---------------------------------------------------------------------------
extern "C" void kernel_launch(void* const* d_in, const int* in_sizes, int n_in,
                              void* d_out, int out_size) {
    const float* probs[NLEV] = {0, 0, 0, 0, 0};
    const float* regs [NLEV] = {0, 0, 0, 0, 0};
    const float* info = 0;

    for (int i = 0; i < n_in; ++i) {
        const float* p = (const float*)d_in[i];
        switch (in_sizes[i]) {
            case 4 * 196608 * 2: probs[0] = p; break;
            case 4 * 196608 * 4: regs [0] = p; break;
            case 4 * 49152 * 2:  probs[1] = p; break;
            case 4 * 49152 * 4:  regs [1] = p; break;
            case 4 * 12288 * 2:  probs[2] = p; break;
            case 4 * 12288 * 4:  regs [2] = p; break;
            case 4 * 3072 * 2:   probs[3] = p; break;
            case 4 * 3072 * 4:   regs [3] = p; break;
            case 4 * 768 * 2:    probs[4] = p; break;
            case 4 * 768 * 4:    regs [4] = p; break;
            case 12:             info = p; break;
            default: break;
        }
    }
    float* out = (float*)d_out;

    topk_kernel<<<NBL, 1024>>>(probs[0], probs[1], probs[2], probs[3], probs[4]);
    decode_kernel<<<dim3(8, NBL), 256>>>(regs[0], regs[1], regs[2], regs[3], regs[4], info);
    nms_mask_kernel<<<dim3(32, 32, NBL), 64>>>();
    nms_reduce_kernel<<<NBL, 1024>>>();
    final_kernel<<<BATCH, 1024>>>(out);
}

// round 4
// speedup vs baseline: 1.8374x; 1.8374x over previous
#include <cuda_runtime.h>
#include <cstdint>

// ---------------------------------------------------------------------------
// Problem constants
// ---------------------------------------------------------------------------
#define NLEV 5
#define BATCH 4
#define PRE_NMS 2000
#define POST_NMS 1000
#define NBL (BATCH * NLEV)          // 20 (batch, level) pairs
#define SORT_CAP 4096               // bitonic capacity for per-level top-k
#define TOTCAT 4768                 // 4*1000 + 768 concatenated entries

__constant__ int c_A[NLEV]      = {196608, 49152, 12288, 3072, 768};
__constant__ int c_K[NLEV]      = {2000, 2000, 2000, 2000, 768};
__constant__ int c_KP[NLEV]     = {1000, 1000, 1000, 1000, 768};
__constant__ int c_stride[NLEV] = {4, 8, 16, 32, 64};
__constant__ int c_grid[NLEV]   = {256, 128, 64, 32, 16};
__constant__ int c_base[NLEV]   = {32, 64, 128, 256, 512};

// ---------------------------------------------------------------------------
// Device scratch (static allocation only — no cudaMalloc allowed)
// ---------------------------------------------------------------------------
__device__ int                 d_topIdx [NBL * PRE_NMS];
__device__ float               d_topScore[NBL * PRE_NMS];
__device__ float4              d_topBoxes[NBL * PRE_NMS];
__device__ unsigned long long  d_mask   [NBL * PRE_NMS * 32];
__device__ float               d_lvlScore[NBL * POST_NMS];
__device__ int                 d_lvlPos  [NBL * POST_NMS];

// ---------------------------------------------------------------------------
// Helpers
// ---------------------------------------------------------------------------
__device__ __forceinline__ unsigned ordf(float f) {
    unsigned u = __float_as_uint(f);
    return (u & 0x80000000u) ? ~u : (u | 0x80000000u);
}
__device__ __forceinline__ float iordf(unsigned u) {
    unsigned v = (u & 0x80000000u) ? (u & 0x7FFFFFFFu) : ~u;
    return __uint_as_float(v);
}

// ---------------------------------------------------------------------------
// Kernel 1: per-(b,l) EXACT top-K selection (R2 version — known-fast).
// 3-pass radix select (11+11+10 bits) -> exact 32-bit threshold T; compact
// u >= T; bitonic sort of 64-bit keys (ordered_score<<32)|~idx.
// ---------------------------------------------------------------------------
__global__ __launch_bounds__(1024)
void topk_kernel(const float* __restrict__ p0, const float* __restrict__ p1,
                 const float* __restrict__ p2, const float* __restrict__ p3,
                 const float* __restrict__ p4) {
    const int bl = blockIdx.x;
    const int b = bl / NLEV, l = bl % NLEV;
    const float* pr;
    switch (l) {
        case 0: pr = p0; break; case 1: pr = p1; break; case 2: pr = p2; break;
        case 3: pr = p3; break; default: pr = p4; break;
    }
    const int A = c_A[l];
    const int K = c_K[l];
    const float* base = pr + (size_t)b * A * 2;
    const int tid = threadIdx.x;

    __shared__ int hist[2048];
    __shared__ unsigned long long cand[SORT_CAP];
    __shared__ int s_b1, s_k1, s_b2, s_k2, s_b3, s_cnt;

    // ---- Pass 1: bits [31:21] ----
    for (int i = tid; i < 2048; i += 1024) hist[i] = 0;
    __syncthreads();
    for (int i = tid; i < A; i += 1024)
        atomicAdd(&hist[ordf(base[2 * i]) >> 21], 1);
    __syncthreads();
    if (tid == 0) {
        int cum = 0, bsel = 0, krem = K;
        for (int bkt = 2047; bkt >= 0; --bkt) {
            int c = hist[bkt];
            if (cum + c >= K) { bsel = bkt; krem = K - cum; break; }
            cum += c;
        }
        s_b1 = bsel; s_k1 = krem;
    }
    __syncthreads();
    const unsigned b1 = (unsigned)s_b1;
    const int K1 = s_k1;

    // ---- Pass 2: bits [20:10] within bucket b1 ----
    for (int i = tid; i < 2048; i += 1024) hist[i] = 0;
    __syncthreads();
    for (int i = tid; i < A; i += 1024) {
        unsigned u = ordf(base[2 * i]);
        if ((u >> 21) == b1) atomicAdd(&hist[(u >> 10) & 0x7FFu], 1);
    }
    __syncthreads();
    if (tid == 0) {
        int cum = 0, bsel = 0, krem = K1;
        for (int bkt = 2047; bkt >= 0; --bkt) {
            int c = hist[bkt];
            if (cum + c >= K1) { bsel = bkt; krem = K1 - cum; break; }
            cum += c;
        }
        s_b2 = bsel; s_k2 = krem;
    }
    __syncthreads();
    const unsigned b2 = (unsigned)s_b2;
    const int K2 = s_k2;
    const unsigned pref2 = (b1 << 11) | b2;

    // ---- Pass 3: bits [9:0] within prefix pref2 ----
    for (int i = tid; i < 1024; i += 1024) hist[i] = 0;
    __syncthreads();
    for (int i = tid; i < A; i += 1024) {
        unsigned u = ordf(base[2 * i]);
        if ((u >> 10) == pref2) atomicAdd(&hist[u & 0x3FFu], 1);
    }
    __syncthreads();
    if (tid == 0) {
        int cum = 0, bsel = 0;
        for (int bkt = 1023; bkt >= 0; --bkt) {
            int c = hist[bkt];
            if (cum + c >= K2) { bsel = bkt; break; }
            cum += c;
        }
        s_b3 = bsel; s_cnt = 0;
    }
    __syncthreads();
    const unsigned T = (b1 << 21) | (b2 << 10) | (unsigned)s_b3;

    // ---- Compact u >= T ----
    for (int i = tid; i < A; i += 1024) {
        unsigned u = ordf(base[2 * i]);
        if (u >= T) {
            int p = atomicAdd(&s_cnt, 1);
            if (p < SORT_CAP)
                cand[p] = ((unsigned long long)u << 32) | (unsigned)(~i);
        }
    }
    __syncthreads();
    const int M = min(s_cnt, SORT_CAP);
    for (int i = tid; i < SORT_CAP; i += 1024)
        if (i >= M) cand[i] = 0ull;
    __syncthreads();

    // ---- Bitonic sort descending (4096 keys) ----
    for (int k = 2; k <= SORT_CAP; k <<= 1) {
        for (int j = k >> 1; j > 0; j >>= 1) {
            for (int idx = tid; idx < SORT_CAP; idx += 1024) {
                int ixj = idx ^ j;
                if (ixj > idx) {
                    unsigned long long a = cand[idx], c2 = cand[ixj];
                    bool desc = (idx & k) == 0;
                    if (desc ? (a < c2) : (a > c2)) { cand[idx] = c2; cand[ixj] = a; }
                }
            }
            __syncthreads();
        }
    }

    for (int j = tid; j < K; j += 1024) {
        unsigned long long key = cand[j];
        d_topIdx [bl * PRE_NMS + j] = (int)(~(unsigned)key);
        d_topScore[bl * PRE_NMS + j] = iordf((unsigned)(key >> 32));
    }
}

// ---------------------------------------------------------------------------
// Kernel 2: decode + clip. All FP via _rn intrinsics (no FMA contraction),
// exp via expf (libdevice) — bit-matches the XLA reference.
// ---------------------------------------------------------------------------
__global__ __launch_bounds__(256)
void decode_kernel(const float* __restrict__ r0, const float* __restrict__ r1,
                   const float* __restrict__ r2, const float* __restrict__ r3,
                   const float* __restrict__ r4, const float* __restrict__ info) {
    const int bl = blockIdx.y;
    const int b = bl / NLEV, l = bl % NLEV;
    const int j = blockIdx.x * 256 + threadIdx.x;
    if (j >= c_K[l]) return;

    const float* rg;
    switch (l) {
        case 0: rg = r0; break; case 1: rg = r1; break; case 2: rg = r2; break;
        case 3: rg = r3; break; default: rg = r4; break;
    }
    const int A = c_A[l];
    const int g = c_grid[l];
    const float strf = (float)c_stride[l];

    const int idx = d_topIdx[bl * PRE_NMS + j];
    const int cell = idx / 3, a = idx - cell * 3;
    const int iy = cell / g, ix = cell - iy * g;

    float cx = __fmul_rn((float)ix + 0.5f, strf);
    float cy = __fmul_rn((float)iy + 0.5f, strf);

    double r = (a == 0) ? 0.5 : ((a == 1) ? 1.0 : 2.0);
    double sb = (double)c_base[l] * 8.0;
    float aw = (float)(sb * sqrt(1.0 / r));
    float ah = (float)(sb * sqrt(r));

    float x1a = __fsub_rn(cx, __fmul_rn(0.5f, aw));
    float y1a = __fsub_rn(cy, __fmul_rn(0.5f, ah));
    float x2a = __fadd_rn(cx, __fmul_rn(0.5f, aw));
    float y2a = __fadd_rn(cy, __fmul_rn(0.5f, ah));

    float wa = __fsub_rn(x2a, x1a);
    float ha = __fsub_rn(y2a, y1a);
    float cxa = __fadd_rn(x1a, __fmul_rn(0.5f, wa));
    float cya = __fadd_rn(y1a, __fmul_rn(0.5f, ha));

    const float* rp = rg + ((size_t)b * A + idx) * 4;
    float dx = rp[0], dy = rp[1], dw = rp[2], dh = rp[3];

    float ncx = __fadd_rn(__fmul_rn(dx, wa), cxa);
    float ncy = __fadd_rn(__fmul_rn(dy, ha), cya);
    float nw  = __fmul_rn(expf(dw), wa);
    float nh  = __fmul_rn(expf(dh), ha);

    float x1 = __fsub_rn(ncx, __fmul_rn(0.5f, nw));
    float y1 = __fsub_rn(ncy, __fmul_rn(0.5f, nh));
    float x2 = __fadd_rn(ncx, __fmul_rn(0.5f, nw));
    float y2 = __fadd_rn(ncy, __fmul_rn(0.5f, nh));

    const float* in2 = info + b * 3;
    float H = __fsub_rn(in2[0], 1.0f);
    float W = __fsub_rn(in2[1], 1.0f);
    x1 = fminf(fmaxf(x1, 0.0f), W);
    x2 = fminf(fmaxf(x2, 0.0f), W);
    y1 = fminf(fmaxf(y1, 0.0f), H);
    y2 = fminf(fmaxf(y2, 0.0f), H);

    d_topBoxes[bl * PRE_NMS + j] = make_float4(x1, y1, x2, y2);
}

// ---------------------------------------------------------------------------
// Kernel 3: NMS suppression-mask — upper-triangular tiles only (bx >= by).
// Lower-triangle words are never read by the reduce.
// ---------------------------------------------------------------------------
__global__ __launch_bounds__(64)
void nms_mask_kernel() {
    if (blockIdx.x < blockIdx.y) return;
    const int bl = blockIdx.z;
    const int l = bl % NLEV;
    const int N = c_K[l];
    const int rowStart = blockIdx.y * 64;
    const int colStart = blockIdx.x * 64;
    if (rowStart >= N || colStart >= N) return;

    __shared__ float4 cbx[64];
    const int t = threadIdx.x;
    int jj = colStart + t;
    cbx[t] = (jj < N) ? d_topBoxes[bl * PRE_NMS + jj] : make_float4(0.f, 0.f, 0.f, 0.f);
    __syncthreads();

    const int i = rowStart + t;
    if (i >= N) return;
    float4 bi = d_topBoxes[bl * PRE_NMS + i];
    float ai = __fmul_rn(fmaxf(__fsub_rn(bi.z, bi.x), 0.0f),
                         fmaxf(__fsub_rn(bi.w, bi.y), 0.0f));
    unsigned long long bits = 0ull;
    #pragma unroll 8
    for (int jl = 0; jl < 64; ++jl) {
        int jg = colStart + jl;
        if (jg <= i || jg >= N) continue;
        float4 bj = cbx[jl];
        float xx1 = fmaxf(bi.x, bj.x), yy1 = fmaxf(bi.y, bj.y);
        float xx2 = fminf(bi.z, bj.z), yy2 = fminf(bi.w, bj.w);
        float w = fmaxf(__fsub_rn(xx2, xx1), 0.0f);
        float h = fmaxf(__fsub_rn(yy2, yy1), 0.0f);
        float inter = __fmul_rn(w, h);
        float aj = __fmul_rn(fmaxf(__fsub_rn(bj.z, bj.x), 0.0f),
                             fmaxf(__fsub_rn(bj.w, bj.y), 0.0f));
        float uni = fmaxf(__fsub_rn(__fadd_rn(ai, aj), inter), 1e-9f);
        float iou = __fdiv_rn(inter, uni);
        if (iou > 0.7f) bits |= (1ull << jl);
    }
    d_mask[((size_t)bl * PRE_NMS + i) * 32 + blockIdx.x] = bits;
}

// ---------------------------------------------------------------------------
// Kernel 4: pipelined warp-specialized NMS reduce.
// 32 warps: warp 0 = serial intra-chunk scan (branch-free arithmetic-mask
// chain) + its own next-column contribution held in registers; warps 1..31
// own future columns, load mask words BEFORE the barrier (static addresses,
// latency hidden), AND with the published keep word, __reduce_or_sync, and
// accumulate into s_rem. One __syncthreads per 64-row chunk.
// ---------------------------------------------------------------------------
__global__ __launch_bounds__(1024)
void nms_reduce_kernel() {
    const int bl = blockIdx.x;
    const int l = bl % NLEV;
    const int N = c_K[l];
    const int KP = c_KP[l];
    const int tid = threadIdx.x;
    const int warp = tid >> 5;
    const int lane = tid & 31;

    __shared__ unsigned long long s_diag[2048];   // padded intra-chunk words
    __shared__ unsigned long long s_rem[32];
    __shared__ unsigned long long s_keep[32];
    __shared__ int sA[2048], sB[2048];

    const unsigned long long* mbase = d_mask + (size_t)bl * PRE_NMS * 32;
    const int NC = (N + 63) >> 6;

    // Stage diagonal-tile words, zero-padded to NC*64 rows.
    for (int i = tid; i < (NC << 6); i += 1024)
        s_diag[i] = (i < N) ? mbase[(size_t)i * 32 + (i >> 6)] : 0ull;
    if (tid < 32) s_rem[tid] = 0ull;
    __syncthreads();

    unsigned long long kreg = 0ull;   // warp 0: previous chunk's keep word

    for (int c = 0; c < NC; ++c) {
        // Issue cross-chunk loads before the barrier (values are static).
        const int cc = c + warp;                   // warp w -> column c+w
        const bool doCol = (c > 0) && (cc < NC);
        unsigned long long m0 = 0ull, m1 = 0ull;
        if (doCol) {
            const int rbase = (c - 1) << 6;
            m0 = mbase[(size_t)(rbase + lane) * 32 + cc];
            m1 = mbase[(size_t)(rbase + 32 + lane) * 32 + cc];
        }
        __syncthreads();   // keep[c-1] visible; s_rem[c] final

        unsigned long long myContrib = 0ull;
        if (doCol) {
            unsigned long long kprev = (warp == 0) ? kreg : s_keep[c - 1];
            unsigned kl = (unsigned)kprev, kh = (unsigned)(kprev >> 32);
            unsigned long long v = 0ull;
            if ((kl >> lane) & 1u) v |= m0;
            if ((kh >> lane) & 1u) v |= m1;
            unsigned vlo = __reduce_or_sync(0xffffffffu, (unsigned)v);
            unsigned vhi = __reduce_or_sync(0xffffffffu, (unsigned)(v >> 32));
            unsigned long long vv = ((unsigned long long)vhi << 32) | vlo;
            if (warp == 0) myContrib = vv;          // column c, used right now
            else if (lane == 0) s_rem[cc] |= vv;    // future columns
        }

        if (warp == 0) {
            unsigned long long rem = s_rem[c] | myContrib;
            unsigned rlo = (unsigned)rem, rhi = (unsigned)(rem >> 32);
            unsigned nklo = 0, nkhi = 0;
            const unsigned long long* dg = s_diag + (c << 6);
            #pragma unroll
            for (int k = 0; k < 32; ++k) {
                unsigned s = (unsigned)((int)(rlo << (31 - k)) >> 31);
                unsigned long long m = dg[k];
                rlo |= (unsigned)m & ~s;
                rhi |= (unsigned)(m >> 32) & ~s;
                nklo |= ~s & (1u << k);
            }
            #pragma unroll
            for (int k = 0; k < 32; ++k) {
                unsigned s = (unsigned)((int)(rhi << (31 - k)) >> 31);
                unsigned long long m = dg[32 + k];
                rhi |= (unsigned)(m >> 32) & ~s;   // rows 32+ suppress only cols 32+
                nkhi |= ~s & (1u << k);
            }
            unsigned long long keepw = ((unsigned long long)nkhi << 32) | nklo;
            const int nr = N - (c << 6);
            if (nr < 64) keepw &= (1ull << nr) - 1ull;
            if (lane == 0) s_keep[c] = keepw;
            kreg = keepw;
        }
    }
    __syncthreads();

    // keep flags -> stable compaction: kept in score order, then suppressed.
    for (int j = tid; j < 2048; j += 1024) {
        int kept = 0;
        if (j < N) kept = (int)((s_keep[j >> 6] >> (j & 63)) & 1ull);
        sA[j] = kept;
    }
    __syncthreads();

    int* src = sA; int* dst = sB;
    for (int off = 1; off < 2048; off <<= 1) {
        for (int j = tid; j < 2048; j += 1024)
            dst[j] = src[j] + ((j >= off) ? src[j - off] : 0);
        __syncthreads();
        int* t = src; src = dst; dst = t;
    }
    const int total = src[2047];

    for (int j = tid; j < N; j += 1024) {
        int kept = (int)((s_keep[j >> 6] >> (j & 63)) & 1ull);
        int incl = src[j];
        if (kept) {
            int rank = incl - 1;
            if (rank < KP) {
                d_lvlScore[bl * POST_NMS + rank] = d_topScore[bl * PRE_NMS + j];
                d_lvlPos  [bl * POST_NMS + rank] = j;
            }
        } else {
            int rank = total + (j - incl);
            if (rank < KP) {
                d_lvlScore[bl * POST_NMS + rank] = -1.0f;
                d_lvlPos  [bl * POST_NMS + rank] = j;
            }
        }
    }
}

// ---------------------------------------------------------------------------
// Kernel 5: final cross-level top-1000 via rank-by-binary-search.
// ---------------------------------------------------------------------------
__global__ __launch_bounds__(1024)
void final_kernel(float* __restrict__ out) {
    const int b = blockIdx.x;
    const int tid = threadIdx.x;
    __shared__ unsigned long long key[TOTCAT];

    for (int c = tid; c < TOTCAT; c += 1024) {
        int l = (c < 4000) ? (c / 1000) : 4;
        int pos = c - l * 1000;
        float s = d_lvlScore[(b * NLEV + l) * POST_NMS + pos];
        key[c] = ((unsigned long long)ordf(s) << 32) | (unsigned)(~c);
    }
    __syncthreads();

    const int segN[NLEV] = {1000, 1000, 1000, 1000, 768};
    for (int c = tid; c < TOTCAT; c += 1024) {
        unsigned long long ke = key[c];
        int rank = 0;
        #pragma unroll
        for (int l2 = 0; l2 < NLEV; ++l2) {
            const int base2 = l2 * 1000;
            int lo = 0, hi = segN[l2];
            while (lo < hi) {
                int mid = (lo + hi) >> 1;
                if (key[base2 + mid] > ke) lo = mid + 1; else hi = mid;
            }
            rank += lo;
        }
        if (rank < POST_NMS) {
            unsigned hi32 = (unsigned)(ke >> 32);
            int l = (c < 4000) ? (c / 1000) : 4;
            int pos = c - l * 1000;
            float* o = out + ((size_t)b * POST_NMS + rank) * 5;
            o[0] = (float)b;
            if (hi32 & 0x80000000u) {   // score >= 0
                int blx = b * NLEV + l;
                int j = d_lvlPos[blx * POST_NMS + pos];
                float4 bx = d_topBoxes[blx * PRE_NMS + j];
                o[1] = bx.x; o[2] = bx.y; o[3] = bx.z; o[4] = bx.w;
            } else {
                o[1] = 0.0f; o[2] = 0.0f; o[3] = 0.0f; o[4] = 0.0f;
            }
        }
    }
}

// ---------------------------------------------------------------------------
// Launcher — inputs identified BY ELEMENT COUNT (all 11 sizes distinct).
// ---------------------------------------------------------------------------
extern "C" void kernel_launch(void* const* d_in, const int* in_sizes, int n_in,
                              void* d_out, int out_size) {
    const float* probs[NLEV] = {0, 0, 0, 0, 0};
    const float* regs [NLEV] = {0, 0, 0, 0, 0};
    const float* info = 0;

    for (int i = 0; i < n_in; ++i) {
        const float* p = (const float*)d_in[i];
        switch (in_sizes[i]) {
            case 4 * 196608 * 2: probs[0] = p; break;
            case 4 * 196608 * 4: regs [0] = p; break;
            case 4 * 49152 * 2:  probs[1] = p; break;
            case 4 * 49152 * 4:  regs [1] = p; break;
            case 4 * 12288 * 2:  probs[2] = p; break;
            case 4 * 12288 * 4:  regs [2] = p; break;
            case 4 * 3072 * 2:   probs[3] = p; break;
            case 4 * 3072 * 4:   regs [3] = p; break;
            case 4 * 768 * 2:    probs[4] = p; break;
            case 4 * 768 * 4:    regs [4] = p; break;
            case 12:             info = p; break;
            default: break;
        }
    }
    float* out = (float*)d_out;

    topk_kernel<<<NBL, 1024>>>(probs[0], probs[1], probs[2], probs[3], probs[4]);
    decode_kernel<<<dim3(8, NBL), 256>>>(regs[0], regs[1], regs[2], regs[3], regs[4], info);
    nms_mask_kernel<<<dim3(32, 32, NBL), 64>>>();
    nms_reduce_kernel<<<NBL, 1024>>>();
    final_kernel<<<BATCH, 1024>>>(out);
}